// round 4
// baseline (speedup 1.0000x reference)
#include <cuda_runtime.h>
#include <cuda_bf16.h>

#define MW_F 1280.0f
#define MH_F 768.0f
#define HH 384
#define WW 640
#define HW (HH*WW)
#define BS 4
#define NBOX 64
#define NB (BS*NBOX)
#define SCALE_F 80.0f
#define MAXRC 104
#define MAXCELLS (MAXRC*MAXRC)
#define P1T 1024

// dynamic smem: vals[MAXCELLS] | hist[2048]
#define SMEM1_BYTES (MAXCELLS*4 + 2048*4)

// Per-box scratch (phase1 -> phase2)
__device__ float g_thr[NB], g_cx[NB], g_cy[NB], g_bw[NB], g_bh[NB], g_score[NB], g_lam[NB];
__device__ int   g_bx[NB], g_by[NB], g_cls[NB];

struct PGeom { float mnx, mxx, mny, mxy, pw, ph; };

// Pinned-rounding pred-box geometry (identical in both phases -> bit-identical IoU)
__device__ __forceinline__ PGeom pred_geom(float p0, float p1, float p2, float p3,
                                           float rx, float ry) {
    float x1 = __fadd_rn(__fmul_rn(p0, SCALE_F), rx);
    float y1 = __fadd_rn(__fmul_rn(p1, SCALE_F), ry);
    float x2 = __fadd_rn(__fmul_rn(p2, SCALE_F), rx);
    float y2 = __fadd_rn(__fmul_rn(p3, SCALE_F), ry);
    float w  = __fsub_rn(x2, x1);
    float h  = __fsub_rn(y2, y1);
    float cx = __fadd_rn(x1, __fmul_rn(w, 0.5f));
    float cy = __fadd_rn(y1, __fmul_rn(h, 0.5f));
    PGeom g;
    g.mnx = __fsub_rn(cx, __fmul_rn(w, 0.5f));
    g.mxx = __fadd_rn(cx, __fmul_rn(w, 0.5f));
    g.mny = __fsub_rn(cy, __fmul_rn(h, 0.5f));
    g.mxy = __fadd_rn(cy, __fmul_rn(h, 0.5f));
    g.pw = w; g.ph = h;
    return g;
}

__device__ __forceinline__ float iou_fn(const PGeom& g, float cx, float cy,
                                        float bw, float bh) {
    float gmnx = __fsub_rn(cx, __fmul_rn(bw, 0.5f));
    float gmxx = __fadd_rn(cx, __fmul_rn(bw, 0.5f));
    float gmny = __fsub_rn(cy, __fmul_rn(bh, 0.5f));
    float gmxy = __fadd_rn(cy, __fmul_rn(bh, 0.5f));
    float iw = fmaxf(__fsub_rn(fminf(g.mxx, gmxx), fmaxf(g.mnx, gmnx)), 0.0f);
    float ih = fmaxf(__fsub_rn(fminf(g.mxy, gmxy), fmaxf(g.mny, gmny)), 0.0f);
    float inter = __fmul_rn(iw, ih);
    float uni = __fsub_rn(__fadd_rn(__fmul_rn(g.pw, g.ph), __fmul_rn(bw, bh)), inter);
    return __fdiv_rn(inter, fmaxf(uni, 1e-6f));
}

// Warp-0-only locate: find bin B with suffix(bins>B) <= want < suffix+hist[B].
// Exactly one lane writes s_bin/s_wrem. Caller syncs around it.
__device__ __forceinline__ void locate_warp(const unsigned* hist, int nbins,
                                            int want, int lane,
                                            int* s_bin, int* s_wrem) {
    const int chunk = nbins >> 5;
    const int base = lane * chunk;
    unsigned partial = 0;
    #pragma unroll 8
    for (int k = 0; k < chunk; k++) partial += hist[base + k];
    // inclusive suffix-sum across lanes
    unsigned suf = partial;
    #pragma unroll
    for (int s = 1; s < 32; s <<= 1) {
        unsigned v = __shfl_down_sync(0xFFFFFFFFu, suf, s);
        if (lane + s < 32) suf += v;
    }
    unsigned running = suf - partial;  // count strictly above this chunk
    for (int k = chunk - 1; k >= 0; k--) {
        unsigned h = hist[base + k];
        if ((unsigned)want >= running && (unsigned)want < running + h) {
            *s_bin = base + k;
            *s_wrem = (int)((unsigned)want - running);
        }
        running += h;
    }
}

// ---------------- Phase 1: per-box region IoU + exact rank-dk threshold ----------------
__global__ __launch_bounds__(P1T) void phase1_kernel(
    const float* __restrict__ pred,    // [BS,4,H,W]
    const float* __restrict__ bboxes,  // [BS,NBOX,6]
    const int*   __restrict__ dmode)
{
    extern __shared__ unsigned char dynbuf[];
    float*    vals = (float*)dynbuf;
    unsigned* hist = (unsigned*)(dynbuf + MAXCELLS * 4);

    __shared__ float s_wsum[32];
    __shared__ int   s_wcnt[32];
    __shared__ int   s_dk, s_P, s_bin, s_wrem;

    const int bn = blockIdx.x;
    const int b = bn / NBOX;
    const int tid = threadIdx.x;
    const int lane = tid & 31;
    const int wid = tid >> 5;

    const float* bx = bboxes + bn * 6;
    float x1 = bx[0], y1 = bx[1], x2 = bx[2], y2 = bx[3], clsf = bx[4], diff = bx[5];
    float bw = __fsub_rn(x2, x1);
    float bh = __fsub_rn(y2, y1);
    float cx = __fadd_rn(x1, __fmul_rn(bw, 0.5f));
    float cy = __fadd_rn(y1, __fmul_rn(bh, 0.5f));
    bool valid = (__fmul_rn(bw, bh) != 0.0f);

    float mnw = floorf(fmaxf(__fsub_rn(__fdiv_rn(__fmul_rn(x1, (float)WW), MW_F), 0.5f), 0.0f));
    float mnh = floorf(fmaxf(__fsub_rn(__fdiv_rn(__fmul_rn(y1, (float)HH), MH_F), 0.5f), 0.0f));
    float mxw = ceilf (fminf(__fsub_rn(__fdiv_rn(__fmul_rn(x2, (float)WW), MW_F), 0.5f), (float)(WW - 1)));
    float mxh = ceilf (fminf(__fsub_rn(__fdiv_rn(__fmul_rn(y2, (float)HH), MH_F), 0.5f), (float)(HH - 1)));
    int ix0 = (int)mnw, ix1 = (int)mxw, iy0 = (int)mnh, iy1 = (int)mxh;
    bool empty = (!valid) || (ix1 < ix0) || (iy1 < iy0);
    int rw = empty ? 0 : (ix1 - ix0 + 1);
    int rh = empty ? 0 : (iy1 - iy0 + 1);
    int cnt = rw * rh;
    if (cnt > MAXCELLS) cnt = MAXCELLS;

    // exact magic-divider for /rw: valid for c<=10815, rw<=104 (c*e < 2^22)
    unsigned inv = (rw > 0) ? (((1u << 22) + (unsigned)rw - 1u) / (unsigned)rw) : 1u;

    // zero level-1 histogram
    #pragma unroll
    for (int h = tid; h < 2048; h += P1T) hist[h] = 0;
    __syncthreads();

    // fused pass: IoU -> vals, sum, positive count, level-1 histogram (bits [31:21])
    float psum = 0.0f;
    int pcount = 0;
    for (int c = tid; c < cnt; c += P1T) {
        int ri = (int)((unsigned)(((unsigned long long)(unsigned)c * inv) >> 22));
        int rj = c - ri * rw;
        int i = iy0 + ri, j = ix0 + rj;
        const float* pb = pred + (b * 4) * HW + i * WW + j;
        float p0 = pb[0 * HW], p1 = pb[1 * HW], p2 = pb[2 * HW], p3 = pb[3 * HW];
        float rx = __fmul_rn(__fadd_rn((float)j, 0.5f), 2.0f);
        float ry = __fmul_rn(__fadd_rn((float)i, 0.5f), 2.0f);
        PGeom g = pred_geom(p0, p1, p2, p3, rx, ry);
        float iou = iou_fn(g, cx, cy, bw, bh);
        vals[c] = iou;
        if (iou > 0.0f) {
            psum += iou;
            pcount++;
            unsigned u = __float_as_uint(iou);
            atomicAdd(&hist[u >> 21], 1u);
        }
    }

    // reduce sum + positive count (32 warps -> warp 0)
    #pragma unroll
    for (int off = 16; off > 0; off >>= 1) {
        psum += __shfl_down_sync(0xFFFFFFFFu, psum, off);
        pcount += __shfl_down_sync(0xFFFFFFFFu, pcount, off);
    }
    if (lane == 0) { s_wsum[wid] = psum; s_wcnt[wid] = pcount; }
    __syncthreads();
    if (wid == 0) {
        float t = s_wsum[lane];
        int   p = s_wcnt[lane];
        #pragma unroll
        for (int off = 16; off > 0; off >>= 1) {
            t += __shfl_down_sync(0xFFFFFFFFu, t, off);
            p += __shfl_down_sync(0xFFFFFFFFu, p, off);
        }
        if (lane == 0) {
            float dkf = ceilf(fmaxf(t, 1.0f));
            if (!(dkf < (float)(HW - 1))) dkf = (float)(HW - 1);
            s_dk = (int)dkf;
            s_P = p;
        }
    }
    __syncthreads();

    const int dk = s_dk;
    const int P = s_P;
    float thr = 0.0f;

    if (dk < P) {
        // level 1: bits [31:21]
        if (wid == 0) locate_warp(hist, 2048, dk, lane, &s_bin, &s_wrem);
        __syncthreads();
        int b1 = s_bin, want2 = s_wrem;
        __syncthreads();

        // level 2: bits [20:10] among values with top bits == b1
        #pragma unroll
        for (int h = tid; h < 2048; h += P1T) hist[h] = 0;
        __syncthreads();
        for (int c = tid; c < cnt; c += P1T) {
            float v = vals[c];
            if (v > 0.0f) {
                unsigned u = __float_as_uint(v);
                if ((int)(u >> 21) == b1) atomicAdd(&hist[(u >> 10) & 0x7FFu], 1u);
            }
        }
        __syncthreads();
        if (wid == 0) locate_warp(hist, 2048, want2, lane, &s_bin, &s_wrem);
        __syncthreads();
        int b2 = s_bin, want3 = s_wrem;
        __syncthreads();

        // level 3: bits [9:0] among values with 22-bit prefix == (b1<<11)|b2
        unsigned pref21 = ((unsigned)b1 << 11) | (unsigned)b2;
        #pragma unroll
        for (int h = tid; h < 1024; h += P1T) hist[h] = 0;
        __syncthreads();
        for (int c = tid; c < cnt; c += P1T) {
            float v = vals[c];
            if (v > 0.0f) {
                unsigned u = __float_as_uint(v);
                if ((u >> 10) == pref21) atomicAdd(&hist[u & 0x3FFu], 1u);
            }
        }
        __syncthreads();
        if (wid == 0) locate_warp(hist, 1024, want3, lane, &s_bin, &s_wrem);
        __syncthreads();
        int b3 = s_bin;

        unsigned uthr = ((unsigned)b1 << 21) | ((unsigned)b2 << 10) | (unsigned)b3;
        thr = __uint_as_float(uthr);
    }

    if (tid == 0) {
        g_thr[bn] = thr;
        g_cx[bn] = cx; g_cy[bn] = cy; g_bw[bn] = bw; g_bh[bn] = bh;
        int dm = *dmode;
        g_score[bn] = dm ? ((diff >= 0.625f) ? 1.0f : 0.0f) : 1.0f;
        g_lam[bn] = 1.0f / sqrtf((float)dk);
        g_cls[bn] = (int)clsf + 1;
        if (empty) { g_bx[bn] = 0xFFFF; g_by[bn] = 0xFFFF; }
        else       { g_bx[bn] = ix0 | (ix1 << 16); g_by[bn] = iy0 | (iy1 << 16); }
    }
}

// ---------------- Phase 2: 4 pixels/thread, vectorized loads & stores ----------------
#define TJ 64
#define TI 16

__global__ __launch_bounds__(256) void phase2_kernel(
    const float* __restrict__ pred,  // [BS,4,H,W]
    float* __restrict__ out)         // cls [BS,H,W,3] then pts [BS,H,W,6]
{
    __shared__ unsigned s_mask[2];
    __shared__ int   s_ncand;
    __shared__ int   s_bxp[NBOX], s_byp[NBOX], s_clsid[NBOX];
    __shared__ float s_thr[NBOX], s_cx[NBOX], s_cy[NBOX], s_bw[NBOX], s_bh[NBOX];
    __shared__ float s_sc[NBOX], s_lm[NBOX];
    __shared__ float s_gmnx[NBOX], s_gmxx[NBOX], s_gmny[NBOX], s_gmxy[NBOX], s_barea[NBOX];

    const int b = blockIdx.z;
    const int j0 = blockIdx.x * TJ;
    const int i0 = blockIdx.y * TI;
    const int tid = threadIdx.x;

    // order-preserving compaction of boxes overlapping this TJ x TI tile
    bool f = false;
    int bxp = 0, byp = 0;
    if (tid < NBOX) {
        int idx = b * NBOX + tid;
        bxp = g_bx[idx]; byp = g_by[idx];
        int x0 = bxp & 0xFFFF, x1 = bxp >> 16;
        int y0 = byp & 0xFFFF, y1 = byp >> 16;
        f = (x0 <= j0 + TJ - 1) && (x1 >= j0) && (y0 <= i0 + TI - 1) && (y1 >= i0);
    }
    unsigned m = __ballot_sync(0xFFFFFFFFu, f);
    if (tid < NBOX && (tid & 31) == 0) s_mask[tid >> 5] = m;
    __syncthreads();
    int base0 = __popc(s_mask[0]);
    if (tid == 0) s_ncand = base0 + __popc(s_mask[1]);
    if (f) {
        int lane = tid & 31;
        int pos = ((tid >> 5) ? base0 : 0) + __popc(m & ((1u << lane) - 1u));
        int idx = b * NBOX + tid;
        float cx = g_cx[idx], cy = g_cy[idx], bw = g_bw[idx], bh = g_bh[idx];
        s_bxp[pos] = bxp; s_byp[pos] = byp;
        s_thr[pos] = g_thr[idx];
        s_cx[pos] = cx; s_cy[pos] = cy; s_bw[pos] = bw; s_bh[pos] = bh;
        s_sc[pos] = g_score[idx]; s_lm[pos] = g_lam[idx];
        s_clsid[pos] = g_cls[idx];
        s_gmnx[pos] = __fsub_rn(cx, __fmul_rn(bw, 0.5f));
        s_gmxx[pos] = __fadd_rn(cx, __fmul_rn(bw, 0.5f));
        s_gmny[pos] = __fsub_rn(cy, __fmul_rn(bh, 0.5f));
        s_gmxy[pos] = __fadd_rn(cy, __fmul_rn(bh, 0.5f));
        s_barea[pos] = __fmul_rn(bw, bh);
    }
    __syncthreads();

    const int jt = j0 + (tid & 15) * 4;   // 4 consecutive columns
    const int it = i0 + (tid >> 4);
    const int pix = it * WW + jt;

    const float* pb = pred + (b * 4) * HW + pix;
    float4 q0 = *(const float4*)(pb + 0 * HW);
    float4 q1 = *(const float4*)(pb + 1 * HW);
    float4 q2 = *(const float4*)(pb + 2 * HW);
    float4 q3 = *(const float4*)(pb + 3 * HW);
    float a0[4] = {q0.x, q0.y, q0.z, q0.w};
    float a1[4] = {q1.x, q1.y, q1.z, q1.w};
    float a2[4] = {q2.x, q2.y, q2.z, q2.w};
    float a3[4] = {q3.x, q3.y, q3.z, q3.w};

    PGeom g[4];
    float parea[4];
    float ry = __fmul_rn(__fadd_rn((float)it, 0.5f), 2.0f);
    #pragma unroll
    for (int u = 0; u < 4; u++) {
        float rx = __fmul_rn(__fadd_rn((float)(jt + u), 0.5f), 2.0f);
        g[u] = pred_geom(a0[u], a1[u], a2[u], a3[u], rx, ry);
        parea[u] = __fmul_rn(g[u].pw, g[u].ph);
    }

    float best[4] = {0.0f, 0.0f, 0.0f, 0.0f};
    int win[4] = {0, 0, 0, 0};
    int cmx[4] = {0, 0, 0, 0};
    bool inreg[4] = {false, false, false, false};

    const int nc = s_ncand;
    for (int k = 0; k < nc; k++) {
        int yp = s_byp[k];
        if (it < (yp & 0xFFFF) || it > (yp >> 16)) continue;
        int bp = s_bxp[k];
        int x0 = bp & 0xFFFF, x1 = bp >> 16;
        float gmnx = s_gmnx[k], gmxx = s_gmxx[k], gmny = s_gmny[k], gmxy = s_gmxy[k];
        float barea = s_barea[k], thrk = s_thr[k];
        #pragma unroll
        for (int u = 0; u < 4; u++) {
            int j = jt + u;
            if (j < x0 || j > x1) continue;
            inreg[u] = true;
            float iw = fmaxf(__fsub_rn(fminf(g[u].mxx, gmxx), fmaxf(g[u].mnx, gmnx)), 0.0f);
            float ih = fmaxf(__fsub_rn(fminf(g[u].mxy, gmxy), fmaxf(g[u].mny, gmny)), 0.0f);
            float inter = __fmul_rn(iw, ih);
            float uni = __fsub_rn(__fadd_rn(parea[u], barea), inter);
            float iou = __fdiv_rn(inter, fmaxf(uni, 1e-6f));
            float kept = (iou > thrk) ? iou : 0.0f;
            if (kept > best[u]) { best[u] = kept; win[u] = k; cmx[u] = 1; }
            else if (kept == best[u] && kept > 0.0f) cmx[u]++;
        }
    }

    // cls output: 4 pixels x 3 = 12 floats = 3x float4
    float cv[12];
    float pv[24];
    #pragma unroll
    for (int u = 0; u < 4; u++) {
        bool assigned = (best[u] > 0.0f);
        float c0, c1, c2;
        if (assigned) {
            if (cmx[u] > 1) { c0 = c1 = c2 = 0.0f; }
            else {
                int ci = s_clsid[win[u]];
                c0 = (ci == 0) ? 1.0f : 0.0f;
                c1 = (ci == 1) ? 1.0f : 0.0f;
                c2 = (ci == 2) ? 1.0f : 0.0f;
            }
        } else if (inreg[u]) {
            c0 = c1 = c2 = 0.0f;
        } else {
            c0 = 1.0f; c1 = 0.0f; c2 = 0.0f;
        }
        cv[u * 3 + 0] = c0; cv[u * 3 + 1] = c1; cv[u * 3 + 2] = c2;

        if (assigned) {
            int w = win[u];
            pv[u * 6 + 0] = s_cx[w]; pv[u * 6 + 1] = s_cy[w];
            pv[u * 6 + 2] = s_bw[w]; pv[u * 6 + 3] = s_bh[w];
            pv[u * 6 + 4] = s_sc[w]; pv[u * 6 + 5] = s_lm[w];
        } else {
            #pragma unroll
            for (int q = 0; q < 6; q++) pv[u * 6 + q] = 1.0f;
        }
    }

    float4* co = (float4*)(out + (size_t)(b * HW + pix) * 3);
    co[0] = make_float4(cv[0], cv[1], cv[2], cv[3]);
    co[1] = make_float4(cv[4], cv[5], cv[6], cv[7]);
    co[2] = make_float4(cv[8], cv[9], cv[10], cv[11]);

    float4* po = (float4*)(out + (size_t)BS * HW * 3 + (size_t)(b * HW + pix) * 6);
    po[0] = make_float4(pv[0], pv[1], pv[2], pv[3]);
    po[1] = make_float4(pv[4], pv[5], pv[6], pv[7]);
    po[2] = make_float4(pv[8], pv[9], pv[10], pv[11]);
    po[3] = make_float4(pv[12], pv[13], pv[14], pv[15]);
    po[4] = make_float4(pv[16], pv[17], pv[18], pv[19]);
    po[5] = make_float4(pv[20], pv[21], pv[22], pv[23]);
}

extern "C" void kernel_launch(void* const* d_in, const int* in_sizes, int n_in,
                              void* d_out, int out_size) {
    // inputs: [0]=feat (unused), [1]=pred, [2]=bboxes, [3]=difficult_mode (int32)
    const float* pred   = (const float*)d_in[1];
    const float* bboxes = (const float*)d_in[2];
    const int*   dmode  = (const int*)d_in[3];
    float* out = (float*)d_out;

    cudaFuncSetAttribute(phase1_kernel, cudaFuncAttributeMaxDynamicSharedMemorySize, SMEM1_BYTES);
    phase1_kernel<<<NB, P1T, SMEM1_BYTES>>>(pred, bboxes, dmode);
    dim3 g2(WW / TJ, HH / TI, BS);
    phase2_kernel<<<g2, 256>>>(pred, out);
}

// round 5
// speedup vs baseline: 1.1497x; 1.1497x over previous
#include <cuda_runtime.h>
#include <cuda_bf16.h>

#define MW_F 1280.0f
#define MH_F 768.0f
#define HH 384
#define WW 640
#define HW (HH*WW)
#define BS 4
#define NBOX 64
#define NB (BS*NBOX)
#define SCALE_F 80.0f
#define MAXRC 104
#define MAXCELLS (MAXRC*MAXRC)
#define P1T 256
#define CANDMAX 4096

// dynamic smem: vals[MAXCELLS] | hist[2048] | cand[CANDMAX]
#define SMEM1_BYTES (MAXCELLS*4 + 2048*4 + CANDMAX*4)

// Per-box scratch (phase1 -> phase2)
__device__ float g_thr[NB], g_cx[NB], g_cy[NB], g_bw[NB], g_bh[NB], g_score[NB], g_lam[NB];
__device__ int   g_bx[NB], g_by[NB], g_cls[NB];

struct PGeom { float mnx, mxx, mny, mxy, pw, ph; };

// Pinned-rounding pred-box geometry (identical in both phases -> bit-identical IoU)
__device__ __forceinline__ PGeom pred_geom(float p0, float p1, float p2, float p3,
                                           float rx, float ry) {
    float x1 = __fadd_rn(__fmul_rn(p0, SCALE_F), rx);
    float y1 = __fadd_rn(__fmul_rn(p1, SCALE_F), ry);
    float x2 = __fadd_rn(__fmul_rn(p2, SCALE_F), rx);
    float y2 = __fadd_rn(__fmul_rn(p3, SCALE_F), ry);
    float w  = __fsub_rn(x2, x1);
    float h  = __fsub_rn(y2, y1);
    float cx = __fadd_rn(x1, __fmul_rn(w, 0.5f));
    float cy = __fadd_rn(y1, __fmul_rn(h, 0.5f));
    PGeom g;
    g.mnx = __fsub_rn(cx, __fmul_rn(w, 0.5f));
    g.mxx = __fadd_rn(cx, __fmul_rn(w, 0.5f));
    g.mny = __fsub_rn(cy, __fmul_rn(h, 0.5f));
    g.mxy = __fadd_rn(cy, __fmul_rn(h, 0.5f));
    g.pw = w; g.ph = h;
    return g;
}

__device__ __forceinline__ float iou_fn(const PGeom& g, float cx, float cy,
                                        float bw, float bh) {
    float gmnx = __fsub_rn(cx, __fmul_rn(bw, 0.5f));
    float gmxx = __fadd_rn(cx, __fmul_rn(bw, 0.5f));
    float gmny = __fsub_rn(cy, __fmul_rn(bh, 0.5f));
    float gmxy = __fadd_rn(cy, __fmul_rn(bh, 0.5f));
    float iw = fmaxf(__fsub_rn(fminf(g.mxx, gmxx), fmaxf(g.mnx, gmnx)), 0.0f);
    float ih = fmaxf(__fsub_rn(fminf(g.mxy, gmxy), fmaxf(g.mny, gmny)), 0.0f);
    float inter = __fmul_rn(iw, ih);
    float uni = __fsub_rn(__fadd_rn(__fmul_rn(g.pw, g.ph), __fmul_rn(bw, bh)), inter);
    return __fdiv_rn(inter, fmaxf(uni, 1e-6f));
}

// Warp-aggregated smem histogram add: one ATOMS per distinct bin per warp.
__device__ __forceinline__ void hist_add(unsigned* hist, unsigned bin, bool valid) {
    unsigned am = __activemask();
    unsigned key = valid ? bin : 0xFFFFFFFFu;
    unsigned mask = __match_any_sync(am, key);
    int leader = __ffs(mask) - 1;
    if (valid && (int)(threadIdx.x & 31) == leader)
        atomicAdd(&hist[bin], __popc(mask));
}

// Warp-0-only locate: find bin B with suffix(bins>B) <= want < suffix+hist[B].
__device__ __forceinline__ void locate_warp(const unsigned* hist, int nbins,
                                            int want, int lane,
                                            int* s_bin, int* s_wrem) {
    const int chunk = nbins >> 5;
    const int base = lane * chunk;
    unsigned partial = 0;
    #pragma unroll 8
    for (int k = 0; k < chunk; k++) partial += hist[base + k];
    unsigned suf = partial;
    #pragma unroll
    for (int s = 1; s < 32; s <<= 1) {
        unsigned v = __shfl_down_sync(0xFFFFFFFFu, suf, s);
        if (lane + s < 32) suf += v;
    }
    unsigned running = suf - partial;
    for (int k = chunk - 1; k >= 0; k--) {
        unsigned h = hist[base + k];
        if ((unsigned)want >= running && (unsigned)want < running + h) {
            *s_bin = base + k;
            *s_wrem = (int)((unsigned)want - running);
        }
        running += h;
    }
}

// ---------------- Phase 1: per-box region IoU + exact rank-dk threshold ----------------
__global__ __launch_bounds__(P1T) void phase1_kernel(
    const float* __restrict__ pred,    // [BS,4,H,W]
    const float* __restrict__ bboxes,  // [BS,NBOX,6]
    const int*   __restrict__ dmode)
{
    extern __shared__ unsigned char dynbuf[];
    float*    vals = (float*)dynbuf;
    unsigned* hist = (unsigned*)(dynbuf + MAXCELLS * 4);
    float*    cand = (float*)(hist + 2048);

    __shared__ float s_wsum[8];
    __shared__ int   s_wcnt[8];
    __shared__ int   s_dk, s_P, s_bin, s_wrem;
    __shared__ int   s_nc;

    const int bn = blockIdx.x;
    const int b = bn / NBOX;
    const int tid = threadIdx.x;
    const int lane = tid & 31;
    const int wid = tid >> 5;

    const float* bx = bboxes + bn * 6;
    float x1 = bx[0], y1 = bx[1], x2 = bx[2], y2 = bx[3], clsf = bx[4], diff = bx[5];
    float bw = __fsub_rn(x2, x1);
    float bh = __fsub_rn(y2, y1);
    float cx = __fadd_rn(x1, __fmul_rn(bw, 0.5f));
    float cy = __fadd_rn(y1, __fmul_rn(bh, 0.5f));
    bool valid = (__fmul_rn(bw, bh) != 0.0f);

    float mnw = floorf(fmaxf(__fsub_rn(__fdiv_rn(__fmul_rn(x1, (float)WW), MW_F), 0.5f), 0.0f));
    float mnh = floorf(fmaxf(__fsub_rn(__fdiv_rn(__fmul_rn(y1, (float)HH), MH_F), 0.5f), 0.0f));
    float mxw = ceilf (fminf(__fsub_rn(__fdiv_rn(__fmul_rn(x2, (float)WW), MW_F), 0.5f), (float)(WW - 1)));
    float mxh = ceilf (fminf(__fsub_rn(__fdiv_rn(__fmul_rn(y2, (float)HH), MH_F), 0.5f), (float)(HH - 1)));
    int ix0 = (int)mnw, ix1 = (int)mxw, iy0 = (int)mnh, iy1 = (int)mxh;
    bool empty = (!valid) || (ix1 < ix0) || (iy1 < iy0);
    int rw = empty ? 0 : (ix1 - ix0 + 1);
    int rh = empty ? 0 : (iy1 - iy0 + 1);
    int cnt = rw * rh;
    if (cnt > MAXCELLS) cnt = MAXCELLS;

    // exact magic-divider for /rw (c<=10815, rw<=104)
    unsigned inv = (rw > 0) ? (((1u << 22) + (unsigned)rw - 1u) / (unsigned)rw) : 1u;

    #pragma unroll
    for (int h = tid; h < 2048; h += P1T) hist[h] = 0;
    __syncthreads();

    // fused pass: IoU -> vals, sum, positive count, level-1 histogram (bits [31:21])
    float psum = 0.0f;
    int pcount = 0;
    const float* pbase = pred + (b * 4) * HW;
    for (int c = tid; c < cnt; c += P1T) {
        int ri = (int)((unsigned)(((unsigned long long)(unsigned)c * inv) >> 22));
        int rj = c - ri * rw;
        int i = iy0 + ri, j = ix0 + rj;
        const float* pb = pbase + i * WW + j;
        float p0 = pb[0 * HW], p1 = pb[1 * HW], p2 = pb[2 * HW], p3 = pb[3 * HW];
        float rx = __fmul_rn(__fadd_rn((float)j, 0.5f), 2.0f);
        float ry = __fmul_rn(__fadd_rn((float)i, 0.5f), 2.0f);
        PGeom g = pred_geom(p0, p1, p2, p3, rx, ry);
        float iou = iou_fn(g, cx, cy, bw, bh);
        vals[c] = iou;
        bool pos = (iou > 0.0f);
        if (pos) { psum += iou; pcount++; }
        hist_add(hist, __float_as_uint(iou) >> 21, pos);
    }

    #pragma unroll
    for (int off = 16; off > 0; off >>= 1) {
        psum += __shfl_down_sync(0xFFFFFFFFu, psum, off);
        pcount += __shfl_down_sync(0xFFFFFFFFu, pcount, off);
    }
    if (lane == 0) { s_wsum[wid] = psum; s_wcnt[wid] = pcount; }
    __syncthreads();
    if (tid == 0) {
        float t = 0.0f; int p = 0;
        #pragma unroll
        for (int w = 0; w < 8; w++) { t += s_wsum[w]; p += s_wcnt[w]; }
        float dkf = ceilf(fmaxf(t, 1.0f));
        if (!(dkf < (float)(HW - 1))) dkf = (float)(HW - 1);
        s_dk = (int)dkf;
        s_P = p;
        s_nc = 0;
    }
    __syncthreads();

    const int dk = s_dk;
    const int P = s_P;
    float thr = 0.0f;

    if (dk < P) {
        // level 1: bits [31:21] (histogram already built)
        if (wid == 0) locate_warp(hist, 2048, dk, lane, &s_bin, &s_wrem);
        __syncthreads();
        int b1 = s_bin, want2 = s_wrem;
        int m = (int)hist[b1];
        __syncthreads();

        bool use_cand = (m <= CANDMAX);
        if (use_cand) {
            // gather candidates in bin b1 (order irrelevant for histogramming)
            for (int c = tid; c < cnt; c += P1T) {
                float v = vals[c];
                if (v > 0.0f && (int)(__float_as_uint(v) >> 21) == b1) {
                    int pos = atomicAdd(&s_nc, 1);
                    cand[pos] = v;
                }
            }
            __syncthreads();
        }
        const float* src = use_cand ? cand : vals;
        const int    n   = use_cand ? m    : cnt;

        // level 2: bits [20:10] among values with top bits == b1
        #pragma unroll
        for (int h = tid; h < 2048; h += P1T) hist[h] = 0;
        __syncthreads();
        for (int c = tid; c < n; c += P1T) {
            float v = src[c];
            unsigned u = __float_as_uint(v);
            bool sel = (v > 0.0f) && ((int)(u >> 21) == b1);
            hist_add(hist, (u >> 10) & 0x7FFu, sel);
        }
        __syncthreads();
        if (wid == 0) locate_warp(hist, 2048, want2, lane, &s_bin, &s_wrem);
        __syncthreads();
        int b2 = s_bin, want3 = s_wrem;
        __syncthreads();

        // level 3: bits [9:0] among values with 22-bit prefix == (b1<<11)|b2
        unsigned pref21 = ((unsigned)b1 << 11) | (unsigned)b2;
        #pragma unroll
        for (int h = tid; h < 1024; h += P1T) hist[h] = 0;
        __syncthreads();
        for (int c = tid; c < n; c += P1T) {
            float v = src[c];
            unsigned u = __float_as_uint(v);
            bool sel = (v > 0.0f) && ((u >> 10) == pref21);
            hist_add(hist, u & 0x3FFu, sel);
        }
        __syncthreads();
        if (wid == 0) locate_warp(hist, 1024, want3, lane, &s_bin, &s_wrem);
        __syncthreads();
        int b3 = s_bin;

        thr = __uint_as_float(((unsigned)b1 << 21) | ((unsigned)b2 << 10) | (unsigned)b3);
    }

    if (tid == 0) {
        g_thr[bn] = thr;
        g_cx[bn] = cx; g_cy[bn] = cy; g_bw[bn] = bw; g_bh[bn] = bh;
        int dm = *dmode;
        g_score[bn] = dm ? ((diff >= 0.625f) ? 1.0f : 0.0f) : 1.0f;
        g_lam[bn] = 1.0f / sqrtf((float)dk);
        g_cls[bn] = (int)clsf + 1;
        if (empty) { g_bx[bn] = 0xFFFF; g_by[bn] = 0xFFFF; }
        else       { g_bx[bn] = ix0 | (ix1 << 16); g_by[bn] = iy0 | (iy1 << 16); }
    }
}

// ---------------- Phase 2: per-pixel argmax/tie across boxes + outputs (R3 version) ----------------
__global__ __launch_bounds__(256) void phase2_kernel(
    const float* __restrict__ pred,  // [BS,4,H,W]
    float* __restrict__ out)         // cls [BS,H,W,3] then pts [BS,H,W,6]
{
    __shared__ unsigned s_mask[2];
    __shared__ int   s_ncand;
    __shared__ int   s_bxp[NBOX], s_byp[NBOX], s_clsid[NBOX];
    __shared__ float s_thr[NBOX], s_cx[NBOX], s_cy[NBOX], s_bw[NBOX], s_bh[NBOX];
    __shared__ float s_sc[NBOX], s_lm[NBOX];

    const int b = blockIdx.z;
    const int j0 = blockIdx.x * 64;
    const int i0 = blockIdx.y * 4;
    const int tid = threadIdx.x;

    bool f = false;
    int bxp = 0, byp = 0;
    if (tid < NBOX) {
        int idx = b * NBOX + tid;
        bxp = g_bx[idx]; byp = g_by[idx];
        int x0 = bxp & 0xFFFF, x1 = bxp >> 16;
        int y0 = byp & 0xFFFF, y1 = byp >> 16;
        f = (x0 <= j0 + 63) && (x1 >= j0) && (y0 <= i0 + 3) && (y1 >= i0);
    }
    unsigned m = __ballot_sync(0xFFFFFFFFu, f);
    if (tid < NBOX && (tid & 31) == 0) s_mask[tid >> 5] = m;
    __syncthreads();
    int base0 = __popc(s_mask[0]);
    if (tid == 0) s_ncand = base0 + __popc(s_mask[1]);
    if (f) {
        int lane = tid & 31;
        int pos = ((tid >> 5) ? base0 : 0) + __popc(m & ((1u << lane) - 1u));
        int idx = b * NBOX + tid;
        s_bxp[pos] = bxp; s_byp[pos] = byp;
        s_thr[pos] = g_thr[idx];
        s_cx[pos] = g_cx[idx]; s_cy[pos] = g_cy[idx];
        s_bw[pos] = g_bw[idx]; s_bh[pos] = g_bh[idx];
        s_sc[pos] = g_score[idx]; s_lm[pos] = g_lam[idx];
        s_clsid[pos] = g_cls[idx];
    }
    __syncthreads();

    const int j = j0 + (tid & 63);
    const int i = i0 + (tid >> 6);
    const int pix = i * WW + j;

    const float* pb = pred + (b * 4) * HW + pix;
    float p0 = pb[0 * HW], p1 = pb[1 * HW], p2 = pb[2 * HW], p3 = pb[3 * HW];
    float rx = __fmul_rn(__fadd_rn((float)j, 0.5f), 2.0f);
    float ry = __fmul_rn(__fadd_rn((float)i, 0.5f), 2.0f);
    PGeom g = pred_geom(p0, p1, p2, p3, rx, ry);

    float best = 0.0f;
    int win = 0;
    int cntmax = 0;
    bool inreg = false;
    const int nc = s_ncand;
    for (int k = 0; k < nc; k++) {
        int bp = s_bxp[k], yp = s_byp[k];
        if (j >= (bp & 0xFFFF) && j <= (bp >> 16) &&
            i >= (yp & 0xFFFF) && i <= (yp >> 16)) {
            inreg = true;
            float iou = iou_fn(g, s_cx[k], s_cy[k], s_bw[k], s_bh[k]);
            float kept = (iou > s_thr[k]) ? iou : 0.0f;
            if (kept > best) { best = kept; win = k; cntmax = 1; }
            else if (kept == best && kept > 0.0f) cntmax++;
        }
    }

    bool assigned = (best > 0.0f);
    float c0, c1, c2;
    if (assigned) {
        if (cntmax > 1) { c0 = c1 = c2 = 0.0f; }
        else {
            int ci = s_clsid[win];
            c0 = (ci == 0) ? 1.0f : 0.0f;
            c1 = (ci == 1) ? 1.0f : 0.0f;
            c2 = (ci == 2) ? 1.0f : 0.0f;
        }
    } else if (inreg) {
        c0 = c1 = c2 = 0.0f;
    } else {
        c0 = 1.0f; c1 = 0.0f; c2 = 0.0f;
    }
    int cidx = (b * HW + pix) * 3;
    out[cidx + 0] = c0; out[cidx + 1] = c1; out[cidx + 2] = c2;

    int pidx = BS * HW * 3 + (b * HW + pix) * 6;
    float2* pv = reinterpret_cast<float2*>(out + pidx);
    if (assigned) {
        pv[0] = make_float2(s_cx[win], s_cy[win]);
        pv[1] = make_float2(s_bw[win], s_bh[win]);
        pv[2] = make_float2(s_sc[win], s_lm[win]);
    } else {
        pv[0] = make_float2(1.0f, 1.0f);
        pv[1] = make_float2(1.0f, 1.0f);
        pv[2] = make_float2(1.0f, 1.0f);
    }
}

extern "C" void kernel_launch(void* const* d_in, const int* in_sizes, int n_in,
                              void* d_out, int out_size) {
    // inputs: [0]=feat (unused), [1]=pred, [2]=bboxes, [3]=difficult_mode (int32)
    const float* pred   = (const float*)d_in[1];
    const float* bboxes = (const float*)d_in[2];
    const int*   dmode  = (const int*)d_in[3];
    float* out = (float*)d_out;

    cudaFuncSetAttribute(phase1_kernel, cudaFuncAttributeMaxDynamicSharedMemorySize, SMEM1_BYTES);
    phase1_kernel<<<NB, P1T, SMEM1_BYTES>>>(pred, bboxes, dmode);
    dim3 g2(WW / 64, HH / 4, BS);
    phase2_kernel<<<g2, 256>>>(pred, out);
}

// round 6
// speedup vs baseline: 1.1656x; 1.0138x over previous
#include <cuda_runtime.h>
#include <cuda_bf16.h>

#define MW_F 1280.0f
#define MH_F 768.0f
#define HH 384
#define WW 640
#define HW (HH*WW)
#define BS 4
#define NBOX 64
#define NB (BS*NBOX)
#define SCALE_F 80.0f
#define MAXRC 104
#define MAXCELLS (MAXRC*MAXRC)
#define P1T 256
#define CANDMAX 4096

// dynamic smem: vals[MAXCELLS] | hist[2048] | cand[CANDMAX]
#define SMEM1_BYTES (MAXCELLS*4 + 2048*4 + CANDMAX*4)

// Per-box scratch (phase1 -> phase2)
__device__ float g_thr[NB], g_cx[NB], g_cy[NB], g_bw[NB], g_bh[NB], g_score[NB], g_lam[NB];
__device__ int   g_bx[NB], g_by[NB], g_cls[NB];

struct PGeom { float mnx, mxx, mny, mxy, pw, ph; };

// Pinned-rounding pred-box geometry (identical in both phases -> bit-identical IoU)
__device__ __forceinline__ PGeom pred_geom(float p0, float p1, float p2, float p3,
                                           float rx, float ry) {
    float x1 = __fadd_rn(__fmul_rn(p0, SCALE_F), rx);
    float y1 = __fadd_rn(__fmul_rn(p1, SCALE_F), ry);
    float x2 = __fadd_rn(__fmul_rn(p2, SCALE_F), rx);
    float y2 = __fadd_rn(__fmul_rn(p3, SCALE_F), ry);
    float w  = __fsub_rn(x2, x1);
    float h  = __fsub_rn(y2, y1);
    float cx = __fadd_rn(x1, __fmul_rn(w, 0.5f));
    float cy = __fadd_rn(y1, __fmul_rn(h, 0.5f));
    PGeom g;
    g.mnx = __fsub_rn(cx, __fmul_rn(w, 0.5f));
    g.mxx = __fadd_rn(cx, __fmul_rn(w, 0.5f));
    g.mny = __fsub_rn(cy, __fmul_rn(h, 0.5f));
    g.mxy = __fadd_rn(cy, __fmul_rn(h, 0.5f));
    g.pw = w; g.ph = h;
    return g;
}

__device__ __forceinline__ float iou_fn(const PGeom& g, float cx, float cy,
                                        float bw, float bh) {
    float gmnx = __fsub_rn(cx, __fmul_rn(bw, 0.5f));
    float gmxx = __fadd_rn(cx, __fmul_rn(bw, 0.5f));
    float gmny = __fsub_rn(cy, __fmul_rn(bh, 0.5f));
    float gmxy = __fadd_rn(cy, __fmul_rn(bh, 0.5f));
    float iw = fmaxf(__fsub_rn(fminf(g.mxx, gmxx), fmaxf(g.mnx, gmnx)), 0.0f);
    float ih = fmaxf(__fsub_rn(fminf(g.mxy, gmxy), fmaxf(g.mny, gmny)), 0.0f);
    float inter = __fmul_rn(iw, ih);
    float uni = __fsub_rn(__fadd_rn(__fmul_rn(g.pw, g.ph), __fmul_rn(bw, bh)), inter);
    return __fdiv_rn(inter, fmaxf(uni, 1e-6f));
}

// Warp-0-only locate: find bin B with suffix(bins>B) <= want < suffix+hist[B].
__device__ __forceinline__ void locate_warp(const unsigned* hist, int nbins,
                                            int want, int lane,
                                            int* s_bin, int* s_wrem) {
    const int chunk = nbins >> 5;
    const int base = lane * chunk;
    unsigned partial = 0;
    #pragma unroll 8
    for (int k = 0; k < chunk; k++) partial += hist[base + k];
    unsigned suf = partial;
    #pragma unroll
    for (int s = 1; s < 32; s <<= 1) {
        unsigned v = __shfl_down_sync(0xFFFFFFFFu, suf, s);
        if (lane + s < 32) suf += v;
    }
    unsigned running = suf - partial;
    for (int k = chunk - 1; k >= 0; k--) {
        unsigned h = hist[base + k];
        if ((unsigned)want >= running && (unsigned)want < running + h) {
            *s_bin = base + k;
            *s_wrem = (int)((unsigned)want - running);
        }
        running += h;
    }
}

__global__ void dummy_kernel() {}

// ---------------- Phase 1: per-box region IoU + exact rank-dk threshold ----------------
__global__ __launch_bounds__(P1T) void phase1_kernel(
    const float* __restrict__ pred,    // [BS,4,H,W]
    const float* __restrict__ bboxes,  // [BS,NBOX,6]
    const int*   __restrict__ dmode)
{
    extern __shared__ unsigned char dynbuf[];
    float*    vals = (float*)dynbuf;
    unsigned* hist = (unsigned*)(dynbuf + MAXCELLS * 4);
    float*    cand = (float*)(hist + 2048);

    __shared__ float s_wsum[8];
    __shared__ int   s_wcnt[8];
    __shared__ int   s_dk, s_P, s_bin, s_wrem;
    __shared__ int   s_nc;

    const int bn = blockIdx.x;
    const int b = bn / NBOX;
    const int tid = threadIdx.x;
    const int lane = tid & 31;
    const int wid = tid >> 5;

    const float* bx = bboxes + bn * 6;
    float x1 = bx[0], y1 = bx[1], x2 = bx[2], y2 = bx[3], clsf = bx[4], diff = bx[5];
    float bw = __fsub_rn(x2, x1);
    float bh = __fsub_rn(y2, y1);
    float cx = __fadd_rn(x1, __fmul_rn(bw, 0.5f));
    float cy = __fadd_rn(y1, __fmul_rn(bh, 0.5f));
    bool valid = (__fmul_rn(bw, bh) != 0.0f);

    float mnw = floorf(fmaxf(__fsub_rn(__fdiv_rn(__fmul_rn(x1, (float)WW), MW_F), 0.5f), 0.0f));
    float mnh = floorf(fmaxf(__fsub_rn(__fdiv_rn(__fmul_rn(y1, (float)HH), MH_F), 0.5f), 0.0f));
    float mxw = ceilf (fminf(__fsub_rn(__fdiv_rn(__fmul_rn(x2, (float)WW), MW_F), 0.5f), (float)(WW - 1)));
    float mxh = ceilf (fminf(__fsub_rn(__fdiv_rn(__fmul_rn(y2, (float)HH), MH_F), 0.5f), (float)(HH - 1)));
    int ix0 = (int)mnw, ix1 = (int)mxw, iy0 = (int)mnh, iy1 = (int)mxh;
    bool empty = (!valid) || (ix1 < ix0) || (iy1 < iy0);
    int rw = empty ? 0 : (ix1 - ix0 + 1);
    int rh = empty ? 0 : (iy1 - iy0 + 1);
    int cnt = rw * rh;
    if (cnt > MAXCELLS) cnt = MAXCELLS;

    // aligned 4-column quads covering [ix0, ix1]
    int qa0 = ix0 >> 2, qa1 = ix1 >> 2;
    int nq = empty ? 0 : (qa1 - qa0 + 1);
    int Q = rh * nq;
    // exact magic-divider for /nq (Q<=2808, nq<=27 -> q*e << 2^22)
    unsigned invq = (nq > 0) ? (((1u << 22) + (unsigned)nq - 1u) / (unsigned)nq) : 1u;

    #pragma unroll
    for (int h = tid; h < 2048; h += P1T) hist[h] = 0;
    __syncthreads();

    // fused vectorized pass: IoU -> vals, sum, pos count, level-1 hist (bits [31:21])
    float psum = 0.0f;
    int pcount = 0;
    const float* pbase = pred + (b * 4) * HW;
    for (int q = tid; q < Q; q += P1T) {
        int ri = (int)((unsigned)(((unsigned long long)(unsigned)q * invq) >> 22));
        int qq = q - ri * nq;
        int i = iy0 + ri;
        int jb = (qa0 + qq) << 2;
        const float* pb = pbase + i * WW + jb;
        float4 r0 = *(const float4*)(pb);
        float4 r1 = *(const float4*)(pb + HW);
        float4 r2 = *(const float4*)(pb + 2 * HW);
        float4 r3 = *(const float4*)(pb + 3 * HW);
        float a0[4] = {r0.x, r0.y, r0.z, r0.w};
        float a1[4] = {r1.x, r1.y, r1.z, r1.w};
        float a2[4] = {r2.x, r2.y, r2.z, r2.w};
        float a3[4] = {r3.x, r3.y, r3.z, r3.w};
        float ry = __fmul_rn(__fadd_rn((float)i, 0.5f), 2.0f);
        int cbase = ri * rw + (jb - ix0);
        #pragma unroll
        for (int u = 0; u < 4; u++) {
            int j = jb + u;
            if (j < ix0 || j > ix1) continue;
            float rx = __fmul_rn(__fadd_rn((float)j, 0.5f), 2.0f);
            PGeom g = pred_geom(a0[u], a1[u], a2[u], a3[u], rx, ry);
            float iou = iou_fn(g, cx, cy, bw, bh);
            vals[cbase + u] = iou;
            if (iou > 0.0f) {
                psum += iou;
                pcount++;
                atomicAdd(&hist[__float_as_uint(iou) >> 21], 1u);
            }
        }
    }

    #pragma unroll
    for (int off = 16; off > 0; off >>= 1) {
        psum += __shfl_down_sync(0xFFFFFFFFu, psum, off);
        pcount += __shfl_down_sync(0xFFFFFFFFu, pcount, off);
    }
    if (lane == 0) { s_wsum[wid] = psum; s_wcnt[wid] = pcount; }
    __syncthreads();
    if (tid == 0) {
        float t = 0.0f; int p = 0;
        #pragma unroll
        for (int w = 0; w < 8; w++) { t += s_wsum[w]; p += s_wcnt[w]; }
        float dkf = ceilf(fmaxf(t, 1.0f));
        if (!(dkf < (float)(HW - 1))) dkf = (float)(HW - 1);
        s_dk = (int)dkf;
        s_P = p;
        s_nc = 0;
    }
    __syncthreads();

    const int dk = s_dk;
    const int P = s_P;
    float thr = 0.0f;

    if (dk < P) {
        // level 1: bits [31:21]
        if (wid == 0) locate_warp(hist, 2048, dk, lane, &s_bin, &s_wrem);
        __syncthreads();
        int b1 = s_bin, want2 = s_wrem;
        int m = (int)hist[b1];
        __syncthreads();

        bool use_cand = (m <= CANDMAX);
        if (use_cand) {
            for (int c = tid; c < cnt; c += P1T) {
                float v = vals[c];
                if (v > 0.0f && (int)(__float_as_uint(v) >> 21) == b1) {
                    int pos = atomicAdd(&s_nc, 1);
                    cand[pos] = v;
                }
            }
            __syncthreads();
        }
        const float* src = use_cand ? cand : vals;
        const int    n   = use_cand ? m    : cnt;

        // level 2: bits [20:10] among values with top bits == b1
        #pragma unroll
        for (int h = tid; h < 2048; h += P1T) hist[h] = 0;
        __syncthreads();
        for (int c = tid; c < n; c += P1T) {
            float v = src[c];
            unsigned u = __float_as_uint(v);
            if (v > 0.0f && (int)(u >> 21) == b1)
                atomicAdd(&hist[(u >> 10) & 0x7FFu], 1u);
        }
        __syncthreads();
        if (wid == 0) locate_warp(hist, 2048, want2, lane, &s_bin, &s_wrem);
        __syncthreads();
        int b2 = s_bin, want3 = s_wrem;
        __syncthreads();

        // level 3: bits [9:0] among values with 22-bit prefix == (b1<<11)|b2
        unsigned pref21 = ((unsigned)b1 << 11) | (unsigned)b2;
        #pragma unroll
        for (int h = tid; h < 1024; h += P1T) hist[h] = 0;
        __syncthreads();
        for (int c = tid; c < n; c += P1T) {
            float v = src[c];
            unsigned u = __float_as_uint(v);
            if (v > 0.0f && (u >> 10) == pref21)
                atomicAdd(&hist[u & 0x3FFu], 1u);
        }
        __syncthreads();
        if (wid == 0) locate_warp(hist, 1024, want3, lane, &s_bin, &s_wrem);
        __syncthreads();
        int b3 = s_bin;

        thr = __uint_as_float(((unsigned)b1 << 21) | ((unsigned)b2 << 10) | (unsigned)b3);
    }

    if (tid == 0) {
        g_thr[bn] = thr;
        g_cx[bn] = cx; g_cy[bn] = cy; g_bw[bn] = bw; g_bh[bn] = bh;
        int dm = *dmode;
        g_score[bn] = dm ? ((diff >= 0.625f) ? 1.0f : 0.0f) : 1.0f;
        g_lam[bn] = 1.0f / sqrtf((float)dk);
        g_cls[bn] = (int)clsf + 1;
        if (empty) { g_bx[bn] = 0xFFFF; g_by[bn] = 0xFFFF; }
        else       { g_bx[bn] = ix0 | (ix1 << 16); g_by[bn] = iy0 | (iy1 << 16); }
    }
}

// ---------------- Phase 2: per-pixel argmax/tie across boxes + outputs ----------------
__global__ __launch_bounds__(256) void phase2_kernel(
    const float* __restrict__ pred,  // [BS,4,H,W]
    float* __restrict__ out)         // cls [BS,H,W,3] then pts [BS,H,W,6]
{
    __shared__ unsigned s_mask[2];
    __shared__ int   s_ncand;
    __shared__ int   s_bxp[NBOX], s_byp[NBOX], s_clsid[NBOX];
    __shared__ float s_thr[NBOX], s_cx[NBOX], s_cy[NBOX], s_bw[NBOX], s_bh[NBOX];
    __shared__ float s_sc[NBOX], s_lm[NBOX];

    const int b = blockIdx.z;
    const int j0 = blockIdx.x * 64;
    const int i0 = blockIdx.y * 4;
    const int tid = threadIdx.x;

    bool f = false;
    int bxp = 0, byp = 0;
    if (tid < NBOX) {
        int idx = b * NBOX + tid;
        bxp = g_bx[idx]; byp = g_by[idx];
        int x0 = bxp & 0xFFFF, x1 = bxp >> 16;
        int y0 = byp & 0xFFFF, y1 = byp >> 16;
        f = (x0 <= j0 + 63) && (x1 >= j0) && (y0 <= i0 + 3) && (y1 >= i0);
    }
    unsigned m = __ballot_sync(0xFFFFFFFFu, f);
    if (tid < NBOX && (tid & 31) == 0) s_mask[tid >> 5] = m;
    __syncthreads();
    int base0 = __popc(s_mask[0]);
    if (tid == 0) s_ncand = base0 + __popc(s_mask[1]);
    if (f) {
        int lane = tid & 31;
        int pos = ((tid >> 5) ? base0 : 0) + __popc(m & ((1u << lane) - 1u));
        int idx = b * NBOX + tid;
        s_bxp[pos] = bxp; s_byp[pos] = byp;
        s_thr[pos] = g_thr[idx];
        s_cx[pos] = g_cx[idx]; s_cy[pos] = g_cy[idx];
        s_bw[pos] = g_bw[idx]; s_bh[pos] = g_bh[idx];
        s_sc[pos] = g_score[idx]; s_lm[pos] = g_lam[idx];
        s_clsid[pos] = g_cls[idx];
    }
    __syncthreads();

    const int j = j0 + (tid & 63);
    const int i = i0 + (tid >> 6);
    const int pix = i * WW + j;

    const float* pb = pred + (b * 4) * HW + pix;
    float p0 = pb[0 * HW], p1 = pb[1 * HW], p2 = pb[2 * HW], p3 = pb[3 * HW];
    float rx = __fmul_rn(__fadd_rn((float)j, 0.5f), 2.0f);
    float ry = __fmul_rn(__fadd_rn((float)i, 0.5f), 2.0f);
    PGeom g = pred_geom(p0, p1, p2, p3, rx, ry);

    float best = 0.0f;
    int win = 0;
    int cntmax = 0;
    bool inreg = false;
    const int nc = s_ncand;
    for (int k = 0; k < nc; k++) {
        int bp = s_bxp[k], yp = s_byp[k];
        if (j >= (bp & 0xFFFF) && j <= (bp >> 16) &&
            i >= (yp & 0xFFFF) && i <= (yp >> 16)) {
            inreg = true;
            float iou = iou_fn(g, s_cx[k], s_cy[k], s_bw[k], s_bh[k]);
            float kept = (iou > s_thr[k]) ? iou : 0.0f;
            if (kept > best) { best = kept; win = k; cntmax = 1; }
            else if (kept == best && kept > 0.0f) cntmax++;
        }
    }

    bool assigned = (best > 0.0f);
    float c0, c1, c2;
    if (assigned) {
        if (cntmax > 1) { c0 = c1 = c2 = 0.0f; }
        else {
            int ci = s_clsid[win];
            c0 = (ci == 0) ? 1.0f : 0.0f;
            c1 = (ci == 1) ? 1.0f : 0.0f;
            c2 = (ci == 2) ? 1.0f : 0.0f;
        }
    } else if (inreg) {
        c0 = c1 = c2 = 0.0f;
    } else {
        c0 = 1.0f; c1 = 0.0f; c2 = 0.0f;
    }
    int cidx = (b * HW + pix) * 3;
    out[cidx + 0] = c0; out[cidx + 1] = c1; out[cidx + 2] = c2;

    int pidx = BS * HW * 3 + (b * HW + pix) * 6;
    float2* pv = reinterpret_cast<float2*>(out + pidx);
    if (assigned) {
        pv[0] = make_float2(s_cx[win], s_cy[win]);
        pv[1] = make_float2(s_bw[win], s_bh[win]);
        pv[2] = make_float2(s_sc[win], s_lm[win]);
    } else {
        pv[0] = make_float2(1.0f, 1.0f);
        pv[1] = make_float2(1.0f, 1.0f);
        pv[2] = make_float2(1.0f, 1.0f);
    }
}

extern "C" void kernel_launch(void* const* d_in, const int* in_sizes, int n_in,
                              void* d_out, int out_size) {
    // inputs: [0]=feat (unused), [1]=pred, [2]=bboxes, [3]=difficult_mode (int32)
    const float* pred   = (const float*)d_in[1];
    const float* bboxes = (const float*)d_in[2];
    const int*   dmode  = (const int*)d_in[3];
    float* out = (float*)d_out;

    cudaFuncSetAttribute(phase1_kernel, cudaFuncAttributeMaxDynamicSharedMemorySize, SMEM1_BYTES);
    // launch pattern (dummy, p1, p2, dummy): period 4, slot 6 == phase1 -> ncu captures phase1
    dummy_kernel<<<1, 32>>>();
    phase1_kernel<<<NB, P1T, SMEM1_BYTES>>>(pred, bboxes, dmode);
    dim3 g2(WW / 64, HH / 4, BS);
    phase2_kernel<<<g2, 256>>>(pred, out);
    dummy_kernel<<<1, 32>>>();
}

// round 8
// speedup vs baseline: 1.3191x; 1.1317x over previous
#include <cuda_runtime.h>
#include <cuda_bf16.h>

#define MW_F 1280.0f
#define MH_F 768.0f
#define HH 384
#define WW 640
#define HW (HH*WW)
#define BS 4
#define NBOX 64
#define NB (BS*NBOX)
#define SCALE_F 80.0f
#define MAXRC 104
#define MAXCELLS (MAXRC*MAXRC)
#define P1T 512

// dynamic smem: vals[MAXCELLS] | hist[2048]
#define SMEM1_BYTES (MAXCELLS*4 + 2048*4)

// Per-box scratch (phase1 -> phase2)
__device__ float g_thr[NB], g_cx[NB], g_cy[NB], g_bw[NB], g_bh[NB], g_score[NB], g_lam[NB];
__device__ int   g_bx[NB], g_by[NB], g_cls[NB];

struct PGeom { float mnx, mxx, mny, mxy, pw, ph; };

// Pinned-rounding pred-box geometry (identical in both phases -> bit-identical IoU)
__device__ __forceinline__ PGeom pred_geom(float p0, float p1, float p2, float p3,
                                           float rx, float ry) {
    float x1 = __fadd_rn(__fmul_rn(p0, SCALE_F), rx);
    float y1 = __fadd_rn(__fmul_rn(p1, SCALE_F), ry);
    float x2 = __fadd_rn(__fmul_rn(p2, SCALE_F), rx);
    float y2 = __fadd_rn(__fmul_rn(p3, SCALE_F), ry);
    float w  = __fsub_rn(x2, x1);
    float h  = __fsub_rn(y2, y1);
    float cx = __fadd_rn(x1, __fmul_rn(w, 0.5f));
    float cy = __fadd_rn(y1, __fmul_rn(h, 0.5f));
    PGeom g;
    g.mnx = __fsub_rn(cx, __fmul_rn(w, 0.5f));
    g.mxx = __fadd_rn(cx, __fmul_rn(w, 0.5f));
    g.mny = __fsub_rn(cy, __fmul_rn(h, 0.5f));
    g.mxy = __fadd_rn(cy, __fmul_rn(h, 0.5f));
    g.pw = w; g.ph = h;
    return g;
}

__device__ __forceinline__ float iou_fn(const PGeom& g, float cx, float cy,
                                        float bw, float bh) {
    float gmnx = __fsub_rn(cx, __fmul_rn(bw, 0.5f));
    float gmxx = __fadd_rn(cx, __fmul_rn(bw, 0.5f));
    float gmny = __fsub_rn(cy, __fmul_rn(bh, 0.5f));
    float gmxy = __fadd_rn(cy, __fmul_rn(bh, 0.5f));
    float iw = fmaxf(__fsub_rn(fminf(g.mxx, gmxx), fmaxf(g.mnx, gmnx)), 0.0f);
    float ih = fmaxf(__fsub_rn(fminf(g.mxy, gmxy), fmaxf(g.mny, gmny)), 0.0f);
    float inter = __fmul_rn(iw, ih);
    float uni = __fsub_rn(__fadd_rn(__fmul_rn(g.pw, g.ph), __fmul_rn(bw, bh)), inter);
    return __fdiv_rn(inter, fmaxf(uni, 1e-6f));
}

// Warp-0-only locate: find bin B with suffix(bins>B) <= want < suffix+hist[B].
__device__ __forceinline__ void locate_warp(const unsigned* hist, int nbins,
                                            int want, int lane,
                                            int* s_bin, int* s_wrem) {
    const int chunk = nbins >> 5;
    const int base = lane * chunk;
    unsigned partial = 0;
    #pragma unroll 8
    for (int k = 0; k < chunk; k++) partial += hist[base + k];
    unsigned suf = partial;
    #pragma unroll
    for (int s = 1; s < 32; s <<= 1) {
        unsigned v = __shfl_down_sync(0xFFFFFFFFu, suf, s);
        if (lane + s < 32) suf += v;
    }
    unsigned running = suf - partial;
    for (int k = chunk - 1; k >= 0; k--) {
        unsigned h = hist[base + k];
        if ((unsigned)want >= running && (unsigned)want < running + h) {
            *s_bin = base + k;
            *s_wrem = (int)((unsigned)want - running);
        }
        running += h;
    }
}

// ---------------- Phase 1: per-box region IoU + exact rank-dk threshold ----------------
__global__ __launch_bounds__(P1T) void phase1_kernel(
    const float* __restrict__ pred,    // [BS,4,H,W]
    const float* __restrict__ bboxes,  // [BS,NBOX,6]
    const int*   __restrict__ dmode)
{
    extern __shared__ unsigned char dynbuf[];
    float*    vals = (float*)dynbuf;
    unsigned* hist = (unsigned*)(dynbuf + MAXCELLS * 4);

    __shared__ float s_wsum[16];
    __shared__ int   s_wcnt[16];
    __shared__ int   s_dk, s_P, s_bin, s_wrem;

    const int bn = blockIdx.x;
    const int b = bn / NBOX;
    const int tid = threadIdx.x;
    const int lane = tid & 31;
    const int wid = tid >> 5;

    const float* bx = bboxes + bn * 6;
    float x1 = bx[0], y1 = bx[1], x2 = bx[2], y2 = bx[3], clsf = bx[4], diff = bx[5];
    float bw = __fsub_rn(x2, x1);
    float bh = __fsub_rn(y2, y1);
    float cx = __fadd_rn(x1, __fmul_rn(bw, 0.5f));
    float cy = __fadd_rn(y1, __fmul_rn(bh, 0.5f));
    bool valid = (__fmul_rn(bw, bh) != 0.0f);

    float mnw = floorf(fmaxf(__fsub_rn(__fdiv_rn(__fmul_rn(x1, (float)WW), MW_F), 0.5f), 0.0f));
    float mnh = floorf(fmaxf(__fsub_rn(__fdiv_rn(__fmul_rn(y1, (float)HH), MH_F), 0.5f), 0.0f));
    float mxw = ceilf (fminf(__fsub_rn(__fdiv_rn(__fmul_rn(x2, (float)WW), MW_F), 0.5f), (float)(WW - 1)));
    float mxh = ceilf (fminf(__fsub_rn(__fdiv_rn(__fmul_rn(y2, (float)HH), MH_F), 0.5f), (float)(HH - 1)));
    int ix0 = (int)mnw, ix1 = (int)mxw, iy0 = (int)mnh, iy1 = (int)mxh;
    bool empty = (!valid) || (ix1 < ix0) || (iy1 < iy0);
    int rw = empty ? 0 : (ix1 - ix0 + 1);
    int rh = empty ? 0 : (iy1 - iy0 + 1);
    int cnt = rw * rh;
    if (cnt > MAXCELLS) cnt = MAXCELLS;

    // aligned 4-column quads covering [ix0, ix1]
    int qa0 = ix0 >> 2, qa1 = ix1 >> 2;
    int nq = empty ? 0 : (qa1 - qa0 + 1);
    int Q = rh * nq;
    // exact magic-divider for /nq (q<=2807, nq<=27 -> q*e < 2^22)
    unsigned invq = (nq > 0) ? (((1u << 22) + (unsigned)nq - 1u) / (unsigned)nq) : 1u;

    // -------- Pass A: pure fused IoU pass, double-buffered prefetch, no atomics --------
    float psum = 0.0f;
    int pcount = 0;
    const float* pbase = pred + (b * 4) * HW;

    int q = tid;
    bool vA = (q < Q);
    int iA = 0, jbA = 0;
    float4 A0, A1, A2, A3;
    if (vA) {
        int ri = (int)((unsigned)(((unsigned long long)(unsigned)q * invq) >> 22));
        int qq = q - ri * nq;
        iA = iy0 + ri; jbA = (qa0 + qq) << 2;
        const float* pb = pbase + iA * WW + jbA;
        A0 = *(const float4*)(pb);
        A1 = *(const float4*)(pb + HW);
        A2 = *(const float4*)(pb + 2 * HW);
        A3 = *(const float4*)(pb + 3 * HW);
    }
    while (vA) {
        int qn = q + P1T;
        bool vB = (qn < Q);
        int iB = 0, jbB = 0;
        float4 B0, B1, B2, B3;
        if (vB) {
            int ri = (int)((unsigned)(((unsigned long long)(unsigned)qn * invq) >> 22));
            int qq = qn - ri * nq;
            iB = iy0 + ri; jbB = (qa0 + qq) << 2;
            const float* pb = pbase + iB * WW + jbB;
            B0 = *(const float4*)(pb);
            B1 = *(const float4*)(pb + HW);
            B2 = *(const float4*)(pb + 2 * HW);
            B3 = *(const float4*)(pb + 3 * HW);
        }
        // process current quad
        {
            float a0[4] = {A0.x, A0.y, A0.z, A0.w};
            float a1[4] = {A1.x, A1.y, A1.z, A1.w};
            float a2[4] = {A2.x, A2.y, A2.z, A2.w};
            float a3[4] = {A3.x, A3.y, A3.z, A3.w};
            float ry = __fmul_rn(__fadd_rn((float)iA, 0.5f), 2.0f);
            int cbase = (iA - iy0) * rw + (jbA - ix0);
            #pragma unroll
            for (int u = 0; u < 4; u++) {
                int j = jbA + u;
                if (j >= ix0 && j <= ix1) {
                    float rx = __fmul_rn(__fadd_rn((float)j, 0.5f), 2.0f);
                    PGeom g = pred_geom(a0[u], a1[u], a2[u], a3[u], rx, ry);
                    float iou = iou_fn(g, cx, cy, bw, bh);
                    vals[cbase + u] = iou;
                    if (iou > 0.0f) { psum += iou; pcount++; }
                }
            }
        }
        q = qn; vA = vB; iA = iB; jbA = jbB;
        A0 = B0; A1 = B1; A2 = B2; A3 = B3;
    }

    // reduce sum + positive count (16 warps)
    #pragma unroll
    for (int off = 16; off > 0; off >>= 1) {
        psum += __shfl_down_sync(0xFFFFFFFFu, psum, off);
        pcount += __shfl_down_sync(0xFFFFFFFFu, pcount, off);
    }
    if (lane == 0) { s_wsum[wid] = psum; s_wcnt[wid] = pcount; }
    __syncthreads();
    if (tid == 0) {
        float t = 0.0f; int p = 0;
        #pragma unroll
        for (int w = 0; w < 16; w++) { t += s_wsum[w]; p += s_wcnt[w]; }
        float dkf = ceilf(fmaxf(t, 1.0f));
        if (!(dkf < (float)(HW - 1))) dkf = (float)(HW - 1);
        s_dk = (int)dkf;
        s_P = p;
    }
    __syncthreads();

    const int dk = s_dk;
    const int P = s_P;
    float thr = 0.0f;

    if (dk < P) {
        // -------- Pass B: level-1 histogram over dense vals (smem-only) --------
        #pragma unroll
        for (int h = tid; h < 2048; h += P1T) hist[h] = 0;
        __syncthreads();
        for (int c = tid; c < cnt; c += P1T) {
            float v = vals[c];
            if (v > 0.0f) atomicAdd(&hist[__float_as_uint(v) >> 21], 1u);
        }
        __syncthreads();
        if (wid == 0) locate_warp(hist, 2048, dk, lane, &s_bin, &s_wrem);
        __syncthreads();
        int b1 = s_bin, want2 = s_wrem;
        __syncthreads();

        // level 2: bits [20:10] among values with top bits == b1
        #pragma unroll
        for (int h = tid; h < 2048; h += P1T) hist[h] = 0;
        __syncthreads();
        for (int c = tid; c < cnt; c += P1T) {
            float v = vals[c];
            unsigned u = __float_as_uint(v);
            if (v > 0.0f && (int)(u >> 21) == b1)
                atomicAdd(&hist[(u >> 10) & 0x7FFu], 1u);
        }
        __syncthreads();
        if (wid == 0) locate_warp(hist, 2048, want2, lane, &s_bin, &s_wrem);
        __syncthreads();
        int b2 = s_bin, want3 = s_wrem;
        __syncthreads();

        // level 3: bits [9:0] among values with 22-bit prefix == (b1<<11)|b2
        unsigned pref21 = ((unsigned)b1 << 11) | (unsigned)b2;
        #pragma unroll
        for (int h = tid; h < 1024; h += P1T) hist[h] = 0;
        __syncthreads();
        for (int c = tid; c < cnt; c += P1T) {
            float v = vals[c];
            unsigned u = __float_as_uint(v);
            if (v > 0.0f && (u >> 10) == pref21)
                atomicAdd(&hist[u & 0x3FFu], 1u);
        }
        __syncthreads();
        if (wid == 0) locate_warp(hist, 1024, want3, lane, &s_bin, &s_wrem);
        __syncthreads();
        int b3 = s_bin;

        thr = __uint_as_float(((unsigned)b1 << 21) | ((unsigned)b2 << 10) | (unsigned)b3);
    }

    if (tid == 0) {
        g_thr[bn] = thr;
        g_cx[bn] = cx; g_cy[bn] = cy; g_bw[bn] = bw; g_bh[bn] = bh;
        int dm = *dmode;
        g_score[bn] = dm ? ((diff >= 0.625f) ? 1.0f : 0.0f) : 1.0f;
        g_lam[bn] = 1.0f / sqrtf((float)dk);
        g_cls[bn] = (int)clsf + 1;
        if (empty) { g_bx[bn] = 0xFFFF; g_by[bn] = 0xFFFF; }
        else       { g_bx[bn] = ix0 | (ix1 << 16); g_by[bn] = iy0 | (iy1 << 16); }
    }
}

// ---------------- Phase 2: per-pixel argmax/tie across boxes + outputs ----------------
__global__ __launch_bounds__(256) void phase2_kernel(
    const float* __restrict__ pred,  // [BS,4,H,W]
    float* __restrict__ out)         // cls [BS,H,W,3] then pts [BS,H,W,6]
{
    __shared__ unsigned s_mask[2];
    __shared__ int   s_ncand;
    __shared__ int   s_bxp[NBOX], s_byp[NBOX], s_clsid[NBOX];
    __shared__ float s_thr[NBOX], s_cx[NBOX], s_cy[NBOX], s_bw[NBOX], s_bh[NBOX];
    __shared__ float s_sc[NBOX], s_lm[NBOX];

    const int b = blockIdx.z;
    const int j0 = blockIdx.x * 64;
    const int i0 = blockIdx.y * 4;
    const int tid = threadIdx.x;

    bool f = false;
    int bxp = 0, byp = 0;
    if (tid < NBOX) {
        int idx = b * NBOX + tid;
        bxp = g_bx[idx]; byp = g_by[idx];
        int x0 = bxp & 0xFFFF, x1 = bxp >> 16;
        int y0 = byp & 0xFFFF, y1 = byp >> 16;
        f = (x0 <= j0 + 63) && (x1 >= j0) && (y0 <= i0 + 3) && (y1 >= i0);
    }
    unsigned m = __ballot_sync(0xFFFFFFFFu, f);
    if (tid < NBOX && (tid & 31) == 0) s_mask[tid >> 5] = m;
    __syncthreads();
    int base0 = __popc(s_mask[0]);
    if (tid == 0) s_ncand = base0 + __popc(s_mask[1]);
    if (f) {
        int lane = tid & 31;
        int pos = ((tid >> 5) ? base0 : 0) + __popc(m & ((1u << lane) - 1u));
        int idx = b * NBOX + tid;
        s_bxp[pos] = bxp; s_byp[pos] = byp;
        s_thr[pos] = g_thr[idx];
        s_cx[pos] = g_cx[idx]; s_cy[pos] = g_cy[idx];
        s_bw[pos] = g_bw[idx]; s_bh[pos] = g_bh[idx];
        s_sc[pos] = g_score[idx]; s_lm[pos] = g_lam[idx];
        s_clsid[pos] = g_cls[idx];
    }
    __syncthreads();

    const int j = j0 + (tid & 63);
    const int i = i0 + (tid >> 6);
    const int pix = i * WW + j;

    const float* pb = pred + (b * 4) * HW + pix;
    float p0 = pb[0 * HW], p1 = pb[1 * HW], p2 = pb[2 * HW], p3 = pb[3 * HW];
    float rx = __fmul_rn(__fadd_rn((float)j, 0.5f), 2.0f);
    float ry = __fmul_rn(__fadd_rn((float)i, 0.5f), 2.0f);
    PGeom g = pred_geom(p0, p1, p2, p3, rx, ry);

    float best = 0.0f;
    int win = 0;
    int cntmax = 0;
    bool inreg = false;
    const int nc = s_ncand;
    for (int k = 0; k < nc; k++) {
        int bp = s_bxp[k], yp = s_byp[k];
        if (j >= (bp & 0xFFFF) && j <= (bp >> 16) &&
            i >= (yp & 0xFFFF) && i <= (yp >> 16)) {
            inreg = true;
            float iou = iou_fn(g, s_cx[k], s_cy[k], s_bw[k], s_bh[k]);
            float kept = (iou > s_thr[k]) ? iou : 0.0f;
            if (kept > best) { best = kept; win = k; cntmax = 1; }
            else if (kept == best && kept > 0.0f) cntmax++;
        }
    }

    bool assigned = (best > 0.0f);
    float c0, c1, c2;
    if (assigned) {
        if (cntmax > 1) { c0 = c1 = c2 = 0.0f; }
        else {
            int ci = s_clsid[win];
            c0 = (ci == 0) ? 1.0f : 0.0f;
            c1 = (ci == 1) ? 1.0f : 0.0f;
            c2 = (ci == 2) ? 1.0f : 0.0f;
        }
    } else if (inreg) {
        c0 = c1 = c2 = 0.0f;
    } else {
        c0 = 1.0f; c1 = 0.0f; c2 = 0.0f;
    }
    int cidx = (b * HW + pix) * 3;
    out[cidx + 0] = c0; out[cidx + 1] = c1; out[cidx + 2] = c2;

    int pidx = BS * HW * 3 + (b * HW + pix) * 6;
    float2* pv = reinterpret_cast<float2*>(out + pidx);
    if (assigned) {
        pv[0] = make_float2(s_cx[win], s_cy[win]);
        pv[1] = make_float2(s_bw[win], s_bh[win]);
        pv[2] = make_float2(s_sc[win], s_lm[win]);
    } else {
        pv[0] = make_float2(1.0f, 1.0f);
        pv[1] = make_float2(1.0f, 1.0f);
        pv[2] = make_float2(1.0f, 1.0f);
    }
}

extern "C" void kernel_launch(void* const* d_in, const int* in_sizes, int n_in,
                              void* d_out, int out_size) {
    // inputs: [0]=feat (unused), [1]=pred, [2]=bboxes, [3]=difficult_mode (int32)
    const float* pred   = (const float*)d_in[1];
    const float* bboxes = (const float*)d_in[2];
    const int*   dmode  = (const int*)d_in[3];
    float* out = (float*)d_out;

    cudaFuncSetAttribute(phase1_kernel, cudaFuncAttributeMaxDynamicSharedMemorySize, SMEM1_BYTES);
    phase1_kernel<<<NB, P1T, SMEM1_BYTES>>>(pred, bboxes, dmode);
    dim3 g2(WW / 64, HH / 4, BS);
    phase2_kernel<<<g2, 256>>>(pred, out);
}